// round 11
// baseline (speedup 1.0000x reference)
#include <cuda_runtime.h>
#include <cstdint>

// R11: last unexplored L2-policy cell. Ten structural variants all sit at the
// same ~7.6us cold floor (= 16.8MB x-read at an invariant ~2.2TB/s; writes are
// L2-absorbed) + ~1.1us graph overhead. Only L2 policy ever moved the warm
// number: load evict_last = 8.608 (best), both sticky = 14.53 (thrash).
// Untested cell: sticky loads + STREAMING stores (st.global.cs) so out lines
// never compete with x for residency.
//
// Math (fixed since R1): RZ phases cancel in |amp|^2 (params unused); CNOT
// chain is XOR-linear; out = [c1c2c3, c0c1, c0c1c2, c0c1c2c3], c_j=cos(x_j).

#define BLOCK 256
#define CPT   4   // 32-byte chunks (2 rows) per thread

struct U4 { unsigned long long a, b, c, d; };   // 256 bits

__device__ __forceinline__ U4 ldg256_evict_last(const void* p)
{
    U4 v;
    asm volatile("ld.global.nc.L2::evict_last.v4.b64 {%0,%1,%2,%3}, [%4];"
                 : "=l"(v.a), "=l"(v.b), "=l"(v.c), "=l"(v.d) : "l"(p));
    return v;
}

__device__ __forceinline__ void stg256_cs(void* p, U4 v)
{
    // streaming (evict-first) store, 256-bit
    asm volatile("st.global.cs.v4.b64 [%0], {%1,%2,%3,%4};"
                 :: "l"(p), "l"(v.a), "l"(v.b), "l"(v.c), "l"(v.d) : "memory");
}

__device__ __forceinline__ float lo_f(unsigned long long u) {
    return __uint_as_float((unsigned)(u & 0xffffffffu));
}
__device__ __forceinline__ float hi_f(unsigned long long u) {
    return __uint_as_float((unsigned)(u >> 32));
}
__device__ __forceinline__ unsigned long long pack_f(float lo, float hi) {
    return (unsigned long long)__float_as_uint(lo)
         | ((unsigned long long)__float_as_uint(hi) << 32);
}

// One 256-bit chunk = two rows [x0 x1 x2 x3 | y0 y1 y2 y3].
__device__ __forceinline__ U4 compute_chunk(U4 v)
{
    float c0 = __cosf(lo_f(v.a)), c1 = __cosf(hi_f(v.a));
    float c2 = __cosf(lo_f(v.b)), c3 = __cosf(hi_f(v.b));
    float c01 = c0 * c1, c012 = c01 * c2;
    U4 o;
    o.a = pack_f(c1 * c2 * c3, c01);
    o.b = pack_f(c012, c012 * c3);
    float d0 = __cosf(lo_f(v.c)), d1 = __cosf(hi_f(v.c));
    float d2 = __cosf(lo_f(v.d)), d3 = __cosf(hi_f(v.d));
    float d01 = d0 * d1, d012 = d01 * d2;
    o.c = pack_f(d1 * d2 * d3, d01);
    o.d = pack_f(d012, d012 * d3);
    return o;
}

__global__ void __launch_bounds__(BLOCK)
_VariationalQHead_65481071396152_kernel(const char* __restrict__ x,
                                        char* __restrict__ out)
{
    int base = blockIdx.x * (BLOCK * CPT) + threadIdx.x;   // 32B-chunk index

    U4 v[CPT];
#pragma unroll
    for (int k = 0; k < CPT; k++)
        v[k] = ldg256_evict_last(x + (size_t)(base + k * BLOCK) * 32);

#pragma unroll
    for (int k = 0; k < CPT; k++) {
        U4 o = compute_chunk(v[k]);
        stg256_cs(out + (size_t)(base + k * BLOCK) * 32, o);
    }
}

// Generic fallback for any residue (dataset is 2^20 rows -> unused there).
__global__ void _VQH_tail_kernel(const float4* __restrict__ x,
                                 float4* __restrict__ out, int start, int n)
{
    int i = start + blockIdx.x * blockDim.x + threadIdx.x;
    if (i < n) {
        float4 v = x[i];
        float c0 = __cosf(v.x), c1 = __cosf(v.y), c2 = __cosf(v.z), c3 = __cosf(v.w);
        float c01 = c0 * c1, c012 = c01 * c2;
        out[i] = make_float4(c1 * c2 * c3, c01, c012, c012 * c3);
    }
}

extern "C" void kernel_launch(void* const* d_in, const int* in_sizes, int n_in,
                              void* d_out, int out_size)
{
    const float4* x = (const float4*)d_in[0];   // x: [B,4] float32
    float4* out = (float4*)d_out;               // out: [B,4] float32
    int n4 = in_sizes[0] / 4;                   // rows (float4 count)
    int nchunks = n4 / 2;                       // 32B chunks (2 rows each)

    int per_block = BLOCK * CPT;
    int grid = nchunks / per_block;             // full tiles, no predicates
    if (grid > 0)
        _VariationalQHead_65481071396152_kernel<<<grid, BLOCK>>>(
            (const char*)x, (char*)out);

    int rem_start = grid * per_block * 2;       // rows covered by main kernel
    int rem = n4 - rem_start;
    if (rem > 0)
        _VQH_tail_kernel<<<(rem + 255) / 256, 256>>>(x, out, rem_start, n4);
}

// round 12
// speedup vs baseline: 1.0611x; 1.0611x over previous
#include <cuda_runtime.h>
#include <cstdint>

// R12: confirmation re-bench of the best configuration (R9, 8.608us).
// Policy matrix complete: evict_last loads + default stores is the best cell;
// streaming stores cost +0.2-0.3; double-sticky thrashes (14.5). Cold floor
// ~7.6us = 16.8MB x-read at the invariant ~2.2TB/s unlocked-clock drain;
// +~1.1us graph-replay overhead. All structural axes exhausted at this floor.
//
// Math (fixed since R1): RZ phases cancel in |amp|^2 (params unused); CNOT
// chain is XOR-linear; out = [c1c2c3, c0c1, c0c1c2, c0c1c2c3], c_j=cos(x_j).
// 4 MUFU.COS + 5 FMUL per row is the information-theoretic minimum compute.

#define BLOCK 256
#define CPT   4   // 32-byte chunks (2 rows) per thread

struct U4 { unsigned long long a, b, c, d; };   // 256 bits

__device__ __forceinline__ U4 ldg256_evict_last(const void* p)
{
    U4 v;
    asm volatile("ld.global.nc.L2::evict_last.v4.b64 {%0,%1,%2,%3}, [%4];"
                 : "=l"(v.a), "=l"(v.b), "=l"(v.c), "=l"(v.d) : "l"(p));
    return v;
}

__device__ __forceinline__ void stg256(void* p, U4 v)
{
    asm volatile("st.global.v4.b64 [%0], {%1,%2,%3,%4};"
                 :: "l"(p), "l"(v.a), "l"(v.b), "l"(v.c), "l"(v.d) : "memory");
}

__device__ __forceinline__ float lo_f(unsigned long long u) {
    return __uint_as_float((unsigned)(u & 0xffffffffu));
}
__device__ __forceinline__ float hi_f(unsigned long long u) {
    return __uint_as_float((unsigned)(u >> 32));
}
__device__ __forceinline__ unsigned long long pack_f(float lo, float hi) {
    return (unsigned long long)__float_as_uint(lo)
         | ((unsigned long long)__float_as_uint(hi) << 32);
}

// One 256-bit chunk = two rows [x0 x1 x2 x3 | y0 y1 y2 y3].
__device__ __forceinline__ U4 compute_chunk(U4 v)
{
    float c0 = __cosf(lo_f(v.a)), c1 = __cosf(hi_f(v.a));
    float c2 = __cosf(lo_f(v.b)), c3 = __cosf(hi_f(v.b));
    float c01 = c0 * c1, c012 = c01 * c2;
    U4 o;
    o.a = pack_f(c1 * c2 * c3, c01);
    o.b = pack_f(c012, c012 * c3);
    float d0 = __cosf(lo_f(v.c)), d1 = __cosf(hi_f(v.c));
    float d2 = __cosf(lo_f(v.d)), d3 = __cosf(hi_f(v.d));
    float d01 = d0 * d1, d012 = d01 * d2;
    o.c = pack_f(d1 * d2 * d3, d01);
    o.d = pack_f(d012, d012 * d3);
    return o;
}

__global__ void __launch_bounds__(BLOCK)
_VariationalQHead_65481071396152_kernel(const char* __restrict__ x,
                                        char* __restrict__ out)
{
    int base = blockIdx.x * (BLOCK * CPT) + threadIdx.x;   // 32B-chunk index

    U4 v[CPT];
#pragma unroll
    for (int k = 0; k < CPT; k++)
        v[k] = ldg256_evict_last(x + (size_t)(base + k * BLOCK) * 32);

#pragma unroll
    for (int k = 0; k < CPT; k++) {
        U4 o = compute_chunk(v[k]);
        stg256(out + (size_t)(base + k * BLOCK) * 32, o);
    }
}

// Generic fallback for any residue (dataset is 2^20 rows -> unused there).
__global__ void _VQH_tail_kernel(const float4* __restrict__ x,
                                 float4* __restrict__ out, int start, int n)
{
    int i = start + blockIdx.x * blockDim.x + threadIdx.x;
    if (i < n) {
        float4 v = x[i];
        float c0 = __cosf(v.x), c1 = __cosf(v.y), c2 = __cosf(v.z), c3 = __cosf(v.w);
        float c01 = c0 * c1, c012 = c01 * c2;
        out[i] = make_float4(c1 * c2 * c3, c01, c012, c012 * c3);
    }
}

extern "C" void kernel_launch(void* const* d_in, const int* in_sizes, int n_in,
                              void* d_out, int out_size)
{
    const float4* x = (const float4*)d_in[0];   // x: [B,4] float32
    float4* out = (float4*)d_out;               // out: [B,4] float32
    int n4 = in_sizes[0] / 4;                   // rows (float4 count)
    int nchunks = n4 / 2;                       // 32B chunks (2 rows each)

    int per_block = BLOCK * CPT;
    int grid = nchunks / per_block;             // full tiles, no predicates
    if (grid > 0)
        _VariationalQHead_65481071396152_kernel<<<grid, BLOCK>>>(
            (const char*)x, (char*)out);

    int rem_start = grid * per_block * 2;       // rows covered by main kernel
    int rem = n4 - rem_start;
    if (rem > 0)
        _VQH_tail_kernel<<<(rem + 255) / 256, 256>>>(x, out, rem_start, n4);
}